// round 16
// baseline (speedup 1.0000x reference)
#include <cuda_runtime.h>
#include <cuda_fp16.h>
#include <cstdint>

#define BATCH   2048
#define NTOK    49
#define DIM     512
#define NHEAD   16
#define HDIM    32
#define NW      64
#define MROWS   (BATCH * NTOK)   // 100352 = 784 * 128
#define QKVCOLS (3 * DIM)        // 1536
#define KD      512

// Scratch (device globals — no cudaMalloc allowed)
__device__ __half g_xh[(size_t)MROWS * KD];
__device__ __half g_wq[QKVCOLS * KD];
__device__ __half g_wp[DIM * KD];
__device__ __half g_qkvh[(size_t)MROWS * QKVCOLS];
__device__ __half g_ah[(size_t)MROWS * DIM];

// ---------------------------------------------------------------------------
// Helpers
// ---------------------------------------------------------------------------
__device__ __forceinline__ uint32_t smem_u32(const void* p) {
    uint32_t a;
    asm("{ .reg .u64 t; cvta.to.shared.u64 t, %1; cvt.u32.u64 %0, t; }"
        : "=r"(a) : "l"(p));
    return a;
}
__device__ __forceinline__ void cp16(uint32_t dst, const void* src) {
    asm volatile("cp.async.cg.shared.global [%0], [%1], 16;"
                 :: "r"(dst), "l"(src));
}
__device__ __forceinline__ void cp_commit() {
    asm volatile("cp.async.commit_group;" ::: "memory");
}
template <int N>
__device__ __forceinline__ void cp_wait() {
    asm volatile("cp.async.wait_group %0;" :: "n"(N) : "memory");
}
__device__ __forceinline__ void mma16816(float* c,
                                         uint32_t a0, uint32_t a1, uint32_t a2, uint32_t a3,
                                         uint32_t b0, uint32_t b1) {
    asm volatile(
        "mma.sync.aligned.m16n8k16.row.col.f32.f16.f16.f32 "
        "{%0,%1,%2,%3}, {%4,%5,%6,%7}, {%8,%9}, {%0,%1,%2,%3};"
        : "+f"(c[0]), "+f"(c[1]), "+f"(c[2]), "+f"(c[3])
        : "r"(a0), "r"(a1), "r"(a2), "r"(a3), "r"(b0), "r"(b1));
}
__device__ __forceinline__ void ldsm_x4(uint32_t* r, uint32_t addr) {
    asm volatile("ldmatrix.sync.aligned.m8n8.x4.shared.b16 {%0,%1,%2,%3}, [%4];"
                 : "=r"(r[0]), "=r"(r[1]), "=r"(r[2]), "=r"(r[3]) : "r"(addr));
}
__device__ __forceinline__ uint32_t f2u(float a, float b) {
    __half2 h = __floats2half2_rn(a, b);
    return *(uint32_t*)&h;
}

// ---------------------------------------------------------------------------
// Conversion kernels
// ---------------------------------------------------------------------------
__global__ void convert_x_kernel(const float* __restrict__ x,
                                 __half* __restrict__ hi, size_t n4) {
    size_t i = (size_t)blockIdx.x * blockDim.x + threadIdx.x;
    if (i >= n4) return;
    float4 v = ((const float4*)x)[i];
    __half2 hp0, hp1;
    hp0.x = __float2half_rn(v.x);
    hp0.y = __float2half_rn(v.y);
    hp1.x = __float2half_rn(v.z);
    hp1.y = __float2half_rn(v.w);
    ((__half2*)hi)[i * 2 + 0] = hp0;
    ((__half2*)hi)[i * 2 + 1] = hp1;
}

__global__ void convert_w_kernel(const float* __restrict__ w,
                                 __half* __restrict__ hi, int K, int N) {
    int idx = blockIdx.x * blockDim.x + threadIdx.x;
    if (idx >= K * N) return;
    int n = idx / K, k = idx - n * K;
    hi[idx] = __float2half_rn(w[(size_t)k * N + n]);
}

// ---------------------------------------------------------------------------
// Single-pass fp16 tensor-core GEMM: C = A[M,K] @ (B[N,K])^T + bias
// CTA tile 128x128, BK=64, 128 threads (4 warps, 2m x 2n), warp tile 64x64.
// 2 CTAs/SM; 2-stage cp.async; ldmatrix.x4 fragment loads (precomputed bases).
// ---------------------------------------------------------------------------
#define SM_STRIDE 144                 // 64 fp16 + 8 pad
#define SM_MAT    (128 * SM_STRIDE)   // 18432 B
#define SM_STAGE  (2 * SM_MAT)        // A + B = 36864 B
#define GEMM_SMEM (2 * SM_STAGE)      // 73728 B

template <bool HALF_OUT>
__global__ void __launch_bounds__(128, 2)
gemm_mma(const __half* __restrict__ Ah, const __half* __restrict__ Bh,
         const float* __restrict__ bias, void* __restrict__ Cv, int N) {
    extern __shared__ char sm[];
    const uint32_t smu = smem_u32(sm);

    const int tid  = threadIdx.x;
    const int lane = tid & 31;
    const int wid  = tid >> 5;
    const int wm   = wid >> 1;         // 0..1 -> 64 rows
    const int wn   = wid & 1;          // 0..1 -> 64 cols
    const int g    = lane >> 2;
    const int tg   = lane & 3;
    const int bn   = blockIdx.x, bm = blockIdx.y;

    const __half* A_p = Ah + (size_t)bm * 128 * KD;
    const __half* B_p = Bh + (size_t)bn * 128 * KD;

    // ldmatrix lane base: lanes 0-15 -> rows, lanes 16-31 -> rows with +16B (k+8)
    const uint32_t lrow = (uint32_t)((lane & 15) * SM_STRIDE + ((lane >> 4) * 16));
    const uint32_t aBase = smu + (uint32_t)(wm * 64 * SM_STRIDE) + lrow;
    const uint32_t bBase = smu + SM_MAT + (uint32_t)(wn * 64 * SM_STRIDE) + lrow;

    // stage load: A 128x64 + B 128x64 = 2048 cp16 over 128 threads
    auto issue_tile = [&](int kt, int buf) {
        const int kof = kt * 64;
        const uint32_t sb = smu + buf * SM_STAGE;
        #pragma unroll
        for (int i = 0; i < 8; i++) {
            const int u = tid + i * 128;
            const int row = u >> 3;
            const int c8 = (u & 7) * 8;
            const uint32_t off = (uint32_t)(row * SM_STRIDE + c8 * 2);
            const size_t go = (size_t)row * KD + kof + c8;
            cp16(sb + off, A_p + go);
            cp16(sb + SM_MAT + off, B_p + go);
        }
    };

    float acc[4][8][4];
    #pragma unroll
    for (int mt = 0; mt < 4; mt++)
        #pragma unroll
        for (int na = 0; na < 8; na++)
            #pragma unroll
            for (int r = 0; r < 4; r++) acc[mt][na][r] = 0.f;

    issue_tile(0, 0);
    cp_commit();

    const int NKT = KD / 64;   // 8
    for (int kt = 0; kt < NKT; kt++) {
        const int buf = kt & 1;
        if (kt + 1 < NKT) {
            issue_tile(kt + 1, buf ^ 1);
            cp_commit();
            cp_wait<1>();
        } else {
            cp_wait<0>();
        }
        __syncthreads();

        const uint32_t sb = (uint32_t)(buf * SM_STAGE);

        #pragma unroll
        for (int ks = 0; ks < 64; ks += 16) {
            const uint32_t ko = sb + (uint32_t)(ks * 2);
            uint32_t a[4][4], bb[4][4];
            #pragma unroll
            for (int mt = 0; mt < 4; mt++)
                ldsm_x4(a[mt], aBase + ko + (uint32_t)(mt * 16 * SM_STRIDE));
            #pragma unroll
            for (int nb = 0; nb < 4; nb++)
                ldsm_x4(bb[nb], bBase + ko + (uint32_t)(nb * 16 * SM_STRIDE));
            #pragma unroll
            for (int nb = 0; nb < 4; nb++) {
                #pragma unroll
                for (int mt = 0; mt < 4; mt++) {
                    mma16816(acc[mt][2 * nb],
                             a[mt][0], a[mt][1], a[mt][2], a[mt][3],
                             bb[nb][0], bb[nb][2]);
                    mma16816(acc[mt][2 * nb + 1],
                             a[mt][0], a[mt][1], a[mt][2], a[mt][3],
                             bb[nb][1], bb[nb][3]);
                }
            }
        }
        __syncthreads();
    }

    #pragma unroll
    for (int mt = 0; mt < 4; mt++) {
        const int row0 = bm * 128 + wm * 64 + mt * 16 + g;
        #pragma unroll
        for (int na = 0; na < 8; na++) {
            const int col = bn * 128 + wn * 64 + na * 8 + tg * 2;
            const float b0 = __ldg(bias + col);
            const float b1 = __ldg(bias + col + 1);
            if (HALF_OUT) {
                __half* Ch = (__half*)Cv;
                __half2 p0 = __floats2half2_rn(acc[mt][na][0] + b0,
                                               acc[mt][na][1] + b1);
                __half2 p1 = __floats2half2_rn(acc[mt][na][2] + b0,
                                               acc[mt][na][3] + b1);
                *(__half2*)(Ch + (size_t)row0 * N + col) = p0;
                *(__half2*)(Ch + (size_t)(row0 + 8) * N + col) = p1;
            } else {
                float* Cf = (float*)Cv;
                float2 o0, o1;
                o0.x = acc[mt][na][0] + b0;
                o0.y = acc[mt][na][1] + b1;
                o1.x = acc[mt][na][2] + b0;
                o1.y = acc[mt][na][3] + b1;
                *(float2*)(Cf + (size_t)row0 * N + col) = o0;
                *(float2*)(Cf + (size_t)(row0 + 8) * N + col) = o1;
            }
        }
    }
}

// ---------------------------------------------------------------------------
// Tensor-core window attention (fp16 qkv input) — unchanged from R13.
// ---------------------------------------------------------------------------
__global__ __launch_bounds__(256)
void window_attn_kernel(const __half* __restrict__ qkv,
                        const float* __restrict__ mask,
                        const float* __restrict__ bias_table,
                        __half* __restrict__ oh) {
    __shared__ __half Qs[2][64 * 40];
    __shared__ __half Ks[2][56 * 40];
    __shared__ __half Vt[2][32 * 72];
    __shared__ float  sbias[2][169];
    __shared__ float  mbuf[NTOK * 50];

    const int b    = blockIdx.x;
    const int tid  = threadIdx.x;
    const int lane = tid & 31;
    const int wid  = tid >> 5;
    const int hh   = wid >> 2;
    const int chunk= wid & 3;
    const int h    = blockIdx.y * 2 + hh;
    const int g    = lane >> 2;
    const int tg   = lane & 3;
    const int t    = tid & 127;
    const int th   = tid >> 7;

    const float scale = rsqrtf((float)HDIM);
    const size_t col0 = (size_t)(blockIdx.y * 2 + th) * HDIM;

    for (int i = t; i < 169; i += 128)
        sbias[th][i] = bias_table[i * NHEAD + (blockIdx.y * 2 + th)];

    const float* mrow = mask + (size_t)(b & (NW - 1)) * NTOK * NTOK;
    for (int idx = tid; idx < NTOK * NTOK; idx += 256) {
        const int i = idx / NTOK;
        const int j = idx - i * NTOK;
        mbuf[i * 50 + j] = mrow[idx];
    }

    for (int idx = t; idx < 64 * 4; idx += 128) {
        const int n  = idx >> 2;
        const int c8 = (idx & 3) * 8;
        uint4 qv = make_uint4(0u, 0u, 0u, 0u);
        uint4 kv = qv, vv = qv;
        if (n < NTOK) {
            const __half* rp = qkv + (size_t)(b * NTOK + n) * QKVCOLS + col0 + c8;
            qv = *(const uint4*)(rp);
            kv = *(const uint4*)(rp + DIM);
            vv = *(const uint4*)(rp + 2 * DIM);
        }
        *(uint4*)&Qs[th][n * 40 + c8] = qv;
        if (n < 56)
            *(uint4*)&Ks[th][n * 40 + c8] = kv;
        const __half* vh = (const __half*)&vv;
        #pragma unroll
        for (int e = 0; e < 8; e++)
            Vt[th][(c8 + e) * 72 + n] = vh[e];
    }
    __syncthreads();

    const int R  = chunk * 16;
    const int i0 = R + g;
    const int i1 = i0 + 8;

    float sacc[7][4];
    #pragma unroll
    for (int nt = 0; nt < 7; nt++)
        #pragma unroll
        for (int r = 0; r < 4; r++) sacc[nt][r] = 0.f;

    #pragma unroll
    for (int s = 0; s < 2; s++) {
        const int ka = 16 * s + 2 * tg;
        const uint32_t a0 = *(const uint32_t*)&Qs[hh][i0 * 40 + ka];
        const uint32_t a1 = *(const uint32_t*)&Qs[hh][i1 * 40 + ka];
        const uint32_t a2 = *(const uint32_t*)&Qs[hh][i0 * 40 + ka + 8];
        const uint32_t a3 = *(const uint32_t*)&Qs[hh][i1 * 40 + ka + 8];
        #pragma unroll
        for (int nt = 0; nt < 7; nt++) {
            const uint32_t b0 = *(const uint32_t*)&Ks[hh][(8 * nt + g) * 40 + ka];
            const uint32_t b1 = *(const uint32_t*)&Ks[hh][(8 * nt + g) * 40 + ka + 8];
            mma16816(sacc[nt], a0, a1, a2, a3, b0, b1);
        }
    }

    const int yi0 = i0 / 7, xi0 = i0 - yi0 * 7;
    const int yi1 = i1 / 7, xi1 = i1 - yi1 * 7;
    #pragma unroll
    for (int nt = 0; nt < 7; nt++) {
        const int j0 = 8 * nt + 2 * tg;
        #pragma unroll
        for (int e = 0; e < 2; e++) {
            const int j = j0 + e;
            if (j >= NTOK) {
                sacc[nt][e]     = -1e30f;
                sacc[nt][e + 2] = -1e30f;
            } else {
                const int yj = j / 7, xj = j - yj * 7;
                if (i0 < NTOK) {
                    const int rel = (yi0 - yj + 6) * 13 + (xi0 - xj + 6);
                    sacc[nt][e] = sacc[nt][e] * scale + sbias[hh][rel] + mbuf[i0 * 50 + j];
                }
                if (i1 < NTOK) {
                    const int rel = (yi1 - yj + 6) * 13 + (xi1 - xj + 6);
                    sacc[nt][e + 2] = sacc[nt][e + 2] * scale + sbias[hh][rel] + mbuf[i1 * 50 + j];
                }
            }
        }
    }

    float m0 = -1e30f, m1 = -1e30f;
    #pragma unroll
    for (int nt = 0; nt < 7; nt++) {
        m0 = fmaxf(m0, fmaxf(sacc[nt][0], sacc[nt][1]));
        m1 = fmaxf(m1, fmaxf(sacc[nt][2], sacc[nt][3]));
    }
    m0 = fmaxf(m0, __shfl_xor_sync(0xffffffffu, m0, 1));
    m0 = fmaxf(m0, __shfl_xor_sync(0xffffffffu, m0, 2));
    m1 = fmaxf(m1, __shfl_xor_sync(0xffffffffu, m1, 1));
    m1 = fmaxf(m1, __shfl_xor_sync(0xffffffffu, m1, 2));

    float sum0 = 0.f, sum1 = 0.f;
    #pragma unroll
    for (int nt = 0; nt < 7; nt++) {
        sacc[nt][0] = __expf(sacc[nt][0] - m0);
        sacc[nt][1] = __expf(sacc[nt][1] - m0);
        sacc[nt][2] = __expf(sacc[nt][2] - m1);
        sacc[nt][3] = __expf(sacc[nt][3] - m1);
        sum0 += sacc[nt][0] + sacc[nt][1];
        sum1 += sacc[nt][2] + sacc[nt][3];
    }
    sum0 += __shfl_xor_sync(0xffffffffu, sum0, 1);
    sum0 += __shfl_xor_sync(0xffffffffu, sum0, 2);
    sum1 += __shfl_xor_sync(0xffffffffu, sum1, 1);
    sum1 += __shfl_xor_sync(0xffffffffu, sum1, 2);
    const float inv0 = 1.f / sum0;
    const float inv1 = 1.f / sum1;

    float oacc[4][4];
    #pragma unroll
    for (int d = 0; d < 4; d++)
        #pragma unroll
        for (int r = 0; r < 4; r++) oacc[d][r] = 0.f;

    #pragma unroll
    for (int s = 0; s < 4; s++) {
        const int t0 = 2 * s, t1 = 2 * s + 1;
        const uint32_t pa0 = f2u(sacc[t0][0] * inv0, sacc[t0][1] * inv0);
        const uint32_t pa1 = f2u(sacc[t0][2] * inv1, sacc[t0][3] * inv1);
        const uint32_t pa2 = (t1 < 7) ? f2u(sacc[t1][0] * inv0, sacc[t1][1] * inv0) : 0u;
        const uint32_t pa3 = (t1 < 7) ? f2u(sacc[t1][2] * inv1, sacc[t1][3] * inv1) : 0u;
        const int kb = 16 * s + 2 * tg;
        #pragma unroll
        for (int d = 0; d < 4; d++) {
            const uint32_t b0 = *(const uint32_t*)&Vt[hh][(8 * d + g) * 72 + kb];
            const uint32_t b1 = *(const uint32_t*)&Vt[hh][(8 * d + g) * 72 + kb + 8];
            mma16816(oacc[d], pa0, pa1, pa2, pa3, b0, b1);
        }
    }

    #pragma unroll
    for (int d = 0; d < 4; d++) {
        const int dc = 8 * d + 2 * tg;
        if (i0 < NTOK) {
            __half2 o = __floats2half2_rn(oacc[d][0], oacc[d][1]);
            *(__half2*)(oh + (size_t)(b * NTOK + i0) * DIM + (size_t)h * HDIM + dc) = o;
        }
        if (i1 < NTOK) {
            __half2 o = __floats2half2_rn(oacc[d][2], oacc[d][3]);
            *(__half2*)(oh + (size_t)(b * NTOK + i1) * DIM + (size_t)h * HDIM + dc) = o;
        }
    }
}

// ---------------------------------------------------------------------------
extern "C" void kernel_launch(void* const* d_in, const int* in_sizes, int n_in,
                              void* d_out, int out_size) {
    const float* x          = (const float*)d_in[0];
    const float* mask       = (const float*)d_in[1];
    const float* qkv_w      = (const float*)d_in[2];
    const float* qkv_b      = (const float*)d_in[3];
    const float* proj_w     = (const float*)d_in[4];
    const float* proj_b     = (const float*)d_in[5];
    const float* bias_table = (const float*)d_in[6];
    float* out = (float*)d_out;

    __half *xh, *wq, *wp, *ah, *qkvh;
    cudaGetSymbolAddress((void**)&xh, g_xh);
    cudaGetSymbolAddress((void**)&wq, g_wq);
    cudaGetSymbolAddress((void**)&wp, g_wp);
    cudaGetSymbolAddress((void**)&ah, g_ah);
    cudaGetSymbolAddress((void**)&qkvh, g_qkvh);

    cudaFuncSetAttribute(gemm_mma<true>,
                         cudaFuncAttributeMaxDynamicSharedMemorySize, GEMM_SMEM);
    cudaFuncSetAttribute(gemm_mma<false>,
                         cudaFuncAttributeMaxDynamicSharedMemorySize, GEMM_SMEM);

    {   // x -> fp16
        const size_t n4 = (size_t)MROWS * KD / 4;
        convert_x_kernel<<<(unsigned)((n4 + 255) / 256), 256>>>(x, xh, n4);
    }
    {   // weights: transpose + fp16
        convert_w_kernel<<<(KD * QKVCOLS + 255) / 256, 256>>>(qkv_w, wq, KD, QKVCOLS);
        convert_w_kernel<<<(KD * DIM + 255) / 256, 256>>>(proj_w, wp, KD, DIM);
    }
    {   // QKV GEMM (tensor cores) -> fp16 intermediate
        dim3 grid(QKVCOLS / 128, MROWS / 128);
        gemm_mma<true><<<grid, 128, GEMM_SMEM>>>(xh, wq, qkv_b, qkvh, QKVCOLS);
    }
    {   // attention (tensor cores): 2 heads per 256-thread block
        dim3 grid(BATCH, NHEAD / 2);
        window_attn_kernel<<<grid, 256>>>(qkvh, mask, bias_table, ah);
    }
    {   // proj GEMM (tensor cores) -> fp32 output
        dim3 grid(DIM / 128, MROWS / 128);
        gemm_mma<false><<<grid, 128, GEMM_SMEM>>>(ah, wp, proj_b, out, DIM);
    }
}

// round 17
// speedup vs baseline: 1.0903x; 1.0903x over previous
#include <cuda_runtime.h>
#include <cuda_fp16.h>
#include <cstdint>

#define BATCH   2048
#define NTOK    49
#define DIM     512
#define NHEAD   16
#define HDIM    32
#define NW      64
#define MROWS   (BATCH * NTOK)   // 100352 = 784 * 128
#define QKVCOLS (3 * DIM)        // 1536
#define KD      512

// Scratch (device globals — no cudaMalloc allowed)
__device__ __half g_xh[(size_t)MROWS * KD];
__device__ __half g_wq[QKVCOLS * KD];
__device__ __half g_wp[DIM * KD];
__device__ __half g_qkvh[(size_t)MROWS * QKVCOLS];
__device__ __half g_ah[(size_t)MROWS * DIM];

// ---------------------------------------------------------------------------
// Helpers
// ---------------------------------------------------------------------------
__device__ __forceinline__ uint32_t smem_u32(const void* p) {
    uint32_t a;
    asm("{ .reg .u64 t; cvta.to.shared.u64 t, %1; cvt.u32.u64 %0, t; }"
        : "=r"(a) : "l"(p));
    return a;
}
__device__ __forceinline__ void cp16(uint32_t dst, const void* src) {
    asm volatile("cp.async.cg.shared.global [%0], [%1], 16;"
                 :: "r"(dst), "l"(src));
}
__device__ __forceinline__ void cp_commit() {
    asm volatile("cp.async.commit_group;" ::: "memory");
}
template <int N>
__device__ __forceinline__ void cp_wait() {
    asm volatile("cp.async.wait_group %0;" :: "n"(N) : "memory");
}
__device__ __forceinline__ void mma16816(float* c,
                                         uint32_t a0, uint32_t a1, uint32_t a2, uint32_t a3,
                                         uint32_t b0, uint32_t b1) {
    asm volatile(
        "mma.sync.aligned.m16n8k16.row.col.f32.f16.f16.f32 "
        "{%0,%1,%2,%3}, {%4,%5,%6,%7}, {%8,%9}, {%0,%1,%2,%3};"
        : "+f"(c[0]), "+f"(c[1]), "+f"(c[2]), "+f"(c[3])
        : "r"(a0), "r"(a1), "r"(a2), "r"(a3), "r"(b0), "r"(b1));
}
__device__ __forceinline__ void ldsm_x4_trans(uint32_t* r, uint32_t addr) {
    asm volatile("ldmatrix.sync.aligned.m8n8.x4.trans.shared.b16 {%0,%1,%2,%3}, [%4];"
                 : "=r"(r[0]), "=r"(r[1]), "=r"(r[2]), "=r"(r[3]) : "r"(addr));
}
__device__ __forceinline__ uint32_t f2u(float a, float b) {
    __half2 h = __floats2half2_rn(a, b);
    return *(uint32_t*)&h;
}

// ---------------------------------------------------------------------------
// Conversion kernels
// ---------------------------------------------------------------------------
__global__ void convert_x_kernel(const float* __restrict__ x,
                                 __half* __restrict__ hi, size_t n4) {
    size_t i = (size_t)blockIdx.x * blockDim.x + threadIdx.x;
    if (i >= n4) return;
    float4 v = ((const float4*)x)[i];
    __half2 hp0, hp1;
    hp0.x = __float2half_rn(v.x);
    hp0.y = __float2half_rn(v.y);
    hp1.x = __float2half_rn(v.z);
    hp1.y = __float2half_rn(v.w);
    ((__half2*)hi)[i * 2 + 0] = hp0;
    ((__half2*)hi)[i * 2 + 1] = hp1;
}

// both weights: w [K,N] fp32 -> fp16 [N,K] (transposed), one launch
__global__ void convert_w2_kernel(const float* __restrict__ wq,
                                  __half* __restrict__ oq,
                                  const float* __restrict__ wp,
                                  __half* __restrict__ op) {
    int idx = blockIdx.x * blockDim.x + threadIdx.x;
    const int nq = KD * QKVCOLS;
    if (idx < nq) {
        int n = idx / KD, k = idx - n * KD;
        oq[idx] = __float2half_rn(wq[(size_t)k * QKVCOLS + n]);
    } else {
        idx -= nq;
        if (idx < KD * DIM) {
            int n = idx / KD, k = idx - n * KD;
            op[idx] = __float2half_rn(wp[(size_t)k * DIM + n]);
        }
    }
}

// ---------------------------------------------------------------------------
// Single-pass fp16 tensor-core GEMM (R15 config — frozen):
// CTA tile 128x128, BK=64, 128 threads (4 warps, 2m x 2n), warp tile 64x64.
// 2 CTAs/SM; 2-stage cp.async; direct-LDS fragment loads.
// ---------------------------------------------------------------------------
#define SM_STRIDE 144                 // 64 fp16 + 8 pad
#define SM_MAT    (128 * SM_STRIDE)   // 18432 B
#define SM_STAGE  (2 * SM_MAT)        // A + B = 36864 B
#define GEMM_SMEM (2 * SM_STAGE)      // 73728 B

template <bool HALF_OUT>
__global__ void __launch_bounds__(128, 2)
gemm_mma(const __half* __restrict__ Ah, const __half* __restrict__ Bh,
         const float* __restrict__ bias, void* __restrict__ Cv, int N) {
    extern __shared__ char sm[];
    const uint32_t smu = smem_u32(sm);

    const int tid  = threadIdx.x;
    const int lane = tid & 31;
    const int wid  = tid >> 5;
    const int wm   = wid >> 1;         // 0..1 -> 64 rows
    const int wn   = wid & 1;          // 0..1 -> 64 cols
    const int g    = lane >> 2;
    const int tg   = lane & 3;
    const int bn   = blockIdx.x, bm = blockIdx.y;

    const __half* A_p = Ah + (size_t)bm * 128 * KD;
    const __half* B_p = Bh + (size_t)bn * 128 * KD;

    auto issue_tile = [&](int kt, int buf) {
        const int kof = kt * 64;
        const uint32_t sb = smu + buf * SM_STAGE;
        #pragma unroll
        for (int i = 0; i < 8; i++) {
            const int u = tid + i * 128;
            const int row = u >> 3;
            const int c8 = (u & 7) * 8;
            const uint32_t off = (uint32_t)(row * SM_STRIDE + c8 * 2);
            const size_t go = (size_t)row * KD + kof + c8;
            cp16(sb + off, A_p + go);
            cp16(sb + SM_MAT + off, B_p + go);
        }
    };

    float acc[4][8][4];
    #pragma unroll
    for (int mt = 0; mt < 4; mt++)
        #pragma unroll
        for (int na = 0; na < 8; na++)
            #pragma unroll
            for (int r = 0; r < 4; r++) acc[mt][na][r] = 0.f;

    issue_tile(0, 0);
    cp_commit();

    const int NKT = KD / 64;   // 8
    for (int kt = 0; kt < NKT; kt++) {
        const int buf = kt & 1;
        if (kt + 1 < NKT) {
            issue_tile(kt + 1, buf ^ 1);
            cp_commit();
            cp_wait<1>();
        } else {
            cp_wait<0>();
        }
        __syncthreads();

        const char* sb = sm + buf * SM_STAGE;
        const char* pA = sb;
        const char* pB = sb + SM_MAT;
        const int m0 = wm * 64;
        const int n0 = wn * 64;

        #pragma unroll
        for (int ks = 0; ks < 64; ks += 16) {
            const int ko = (ks + tg * 2) * 2;
            uint32_t a[4][4];
            #pragma unroll
            for (int mt = 0; mt < 4; mt++) {
                const int rb = (m0 + mt * 16 + g) * SM_STRIDE;
                a[mt][0] = *(const uint32_t*)(pA + rb + ko);
                a[mt][1] = *(const uint32_t*)(pA + rb + 8 * SM_STRIDE + ko);
                a[mt][2] = *(const uint32_t*)(pA + rb + ko + 16);
                a[mt][3] = *(const uint32_t*)(pA + rb + 8 * SM_STRIDE + ko + 16);
            }
            #pragma unroll
            for (int na = 0; na < 8; na++) {
                const int nb = (n0 + na * 8 + g) * SM_STRIDE;
                const uint32_t b0 = *(const uint32_t*)(pB + nb + ko);
                const uint32_t b1 = *(const uint32_t*)(pB + nb + ko + 16);
                #pragma unroll
                for (int mt = 0; mt < 4; mt++)
                    mma16816(acc[mt][na], a[mt][0], a[mt][1], a[mt][2], a[mt][3], b0, b1);
            }
        }
        __syncthreads();
    }

    #pragma unroll
    for (int mt = 0; mt < 4; mt++) {
        const int row0 = bm * 128 + wm * 64 + mt * 16 + g;
        #pragma unroll
        for (int na = 0; na < 8; na++) {
            const int col = bn * 128 + wn * 64 + na * 8 + tg * 2;
            const float b0 = __ldg(bias + col);
            const float b1 = __ldg(bias + col + 1);
            if (HALF_OUT) {
                __half* Ch = (__half*)Cv;
                __half2 p0 = __floats2half2_rn(acc[mt][na][0] + b0,
                                               acc[mt][na][1] + b1);
                __half2 p1 = __floats2half2_rn(acc[mt][na][2] + b0,
                                               acc[mt][na][3] + b1);
                *(__half2*)(Ch + (size_t)row0 * N + col) = p0;
                *(__half2*)(Ch + (size_t)(row0 + 8) * N + col) = p1;
            } else {
                float* Cf = (float*)Cv;
                float2 o0, o1;
                o0.x = acc[mt][na][0] + b0;
                o0.y = acc[mt][na][1] + b1;
                o1.x = acc[mt][na][2] + b0;
                o1.y = acc[mt][na][3] + b1;
                *(float2*)(Cf + (size_t)row0 * N + col) = o0;
                *(float2*)(Cf + (size_t)(row0 + 8) * N + col) = o1;
            }
        }
    }
}

// ---------------------------------------------------------------------------
// Tensor-core window attention: V stored ROW-major (uint4 STS like Q), PV
// B-fragments via ldmatrix.x4.trans (no scalar transpose scatter).
// 256 threads = 8 warps = 2 heads x 4 chunks.
// ---------------------------------------------------------------------------
__global__ __launch_bounds__(256)
void window_attn_kernel(const __half* __restrict__ qkv,
                        const float* __restrict__ mask,
                        const float* __restrict__ bias_table,
                        __half* __restrict__ oh) {
    __shared__ __half Qs[2][64 * 40];    // [row][d], stride 40 halfs
    __shared__ __half Ks[2][56 * 40];
    __shared__ __half Vs[2][64 * 40];    // row-major V
    __shared__ float  sbias[2][169];
    __shared__ float  mbuf[NTOK * 50];

    const int b    = blockIdx.x;
    const int tid  = threadIdx.x;
    const int lane = tid & 31;
    const int wid  = tid >> 5;
    const int hh   = wid >> 2;
    const int chunk= wid & 3;
    const int h    = blockIdx.y * 2 + hh;
    const int g    = lane >> 2;
    const int tg   = lane & 3;
    const int t    = tid & 127;
    const int th   = tid >> 7;

    const float scale = rsqrtf((float)HDIM);
    const size_t col0 = (size_t)(blockIdx.y * 2 + th) * HDIM;

    for (int i = t; i < 169; i += 128)
        sbias[th][i] = bias_table[i * NHEAD + (blockIdx.y * 2 + th)];

    const float* mrow = mask + (size_t)(b & (NW - 1)) * NTOK * NTOK;
    for (int idx = tid; idx < NTOK * NTOK; idx += 256) {
        const int i = idx / NTOK;
        const int j = idx - i * NTOK;
        mbuf[i * 50 + j] = mrow[idx];
    }

    for (int idx = t; idx < 64 * 4; idx += 128) {
        const int n  = idx >> 2;
        const int c8 = (idx & 3) * 8;
        uint4 qv = make_uint4(0u, 0u, 0u, 0u);
        uint4 kv = qv, vv = qv;
        if (n < NTOK) {
            const __half* rp = qkv + (size_t)(b * NTOK + n) * QKVCOLS + col0 + c8;
            qv = *(const uint4*)(rp);
            kv = *(const uint4*)(rp + DIM);
            vv = *(const uint4*)(rp + 2 * DIM);
        }
        *(uint4*)&Qs[th][n * 40 + c8] = qv;
        if (n < 56)
            *(uint4*)&Ks[th][n * 40 + c8] = kv;
        *(uint4*)&Vs[th][n * 40 + c8] = vv;
    }
    __syncthreads();

    const int R  = chunk * 16;
    const int i0 = R + g;
    const int i1 = i0 + 8;

    // QK^T: S[16,56] over 7 n-tiles, 2 k-steps
    float sacc[7][4];
    #pragma unroll
    for (int nt = 0; nt < 7; nt++)
        #pragma unroll
        for (int r = 0; r < 4; r++) sacc[nt][r] = 0.f;

    #pragma unroll
    for (int s = 0; s < 2; s++) {
        const int ka = 16 * s + 2 * tg;
        const uint32_t a0 = *(const uint32_t*)&Qs[hh][i0 * 40 + ka];
        const uint32_t a1 = *(const uint32_t*)&Qs[hh][i1 * 40 + ka];
        const uint32_t a2 = *(const uint32_t*)&Qs[hh][i0 * 40 + ka + 8];
        const uint32_t a3 = *(const uint32_t*)&Qs[hh][i1 * 40 + ka + 8];
        #pragma unroll
        for (int nt = 0; nt < 7; nt++) {
            const uint32_t b0 = *(const uint32_t*)&Ks[hh][(8 * nt + g) * 40 + ka];
            const uint32_t b1 = *(const uint32_t*)&Ks[hh][(8 * nt + g) * 40 + ka + 8];
            mma16816(sacc[nt], a0, a1, a2, a3, b0, b1);
        }
    }

    // scale + bias + mask + column padding
    const int yi0 = i0 / 7, xi0 = i0 - yi0 * 7;
    const int yi1 = i1 / 7, xi1 = i1 - yi1 * 7;
    #pragma unroll
    for (int nt = 0; nt < 7; nt++) {
        const int j0 = 8 * nt + 2 * tg;
        #pragma unroll
        for (int e = 0; e < 2; e++) {
            const int j = j0 + e;
            if (j >= NTOK) {
                sacc[nt][e]     = -1e30f;
                sacc[nt][e + 2] = -1e30f;
            } else {
                const int yj = j / 7, xj = j - yj * 7;
                if (i0 < NTOK) {
                    const int rel = (yi0 - yj + 6) * 13 + (xi0 - xj + 6);
                    sacc[nt][e] = sacc[nt][e] * scale + sbias[hh][rel] + mbuf[i0 * 50 + j];
                }
                if (i1 < NTOK) {
                    const int rel = (yi1 - yj + 6) * 13 + (xi1 - xj + 6);
                    sacc[nt][e + 2] = sacc[nt][e + 2] * scale + sbias[hh][rel] + mbuf[i1 * 50 + j];
                }
            }
        }
    }

    // register softmax
    float m0 = -1e30f, m1 = -1e30f;
    #pragma unroll
    for (int nt = 0; nt < 7; nt++) {
        m0 = fmaxf(m0, fmaxf(sacc[nt][0], sacc[nt][1]));
        m1 = fmaxf(m1, fmaxf(sacc[nt][2], sacc[nt][3]));
    }
    m0 = fmaxf(m0, __shfl_xor_sync(0xffffffffu, m0, 1));
    m0 = fmaxf(m0, __shfl_xor_sync(0xffffffffu, m0, 2));
    m1 = fmaxf(m1, __shfl_xor_sync(0xffffffffu, m1, 1));
    m1 = fmaxf(m1, __shfl_xor_sync(0xffffffffu, m1, 2));

    float sum0 = 0.f, sum1 = 0.f;
    #pragma unroll
    for (int nt = 0; nt < 7; nt++) {
        sacc[nt][0] = __expf(sacc[nt][0] - m0);
        sacc[nt][1] = __expf(sacc[nt][1] - m0);
        sacc[nt][2] = __expf(sacc[nt][2] - m1);
        sacc[nt][3] = __expf(sacc[nt][3] - m1);
        sum0 += sacc[nt][0] + sacc[nt][1];
        sum1 += sacc[nt][2] + sacc[nt][3];
    }
    sum0 += __shfl_xor_sync(0xffffffffu, sum0, 1);
    sum0 += __shfl_xor_sync(0xffffffffu, sum0, 2);
    sum1 += __shfl_xor_sync(0xffffffffu, sum1, 1);
    sum1 += __shfl_xor_sync(0xffffffffu, sum1, 2);
    const float inv0 = 1.f / sum0;
    const float inv1 = 1.f / sum1;

    // PV: O[16,32] = P[16,64] @ V[64,32]; V fragments via ldmatrix.trans.
    // Per k-step s (16 j's): two ldsm.x4.trans cover all 4 d-tiles.
    // Lane address: row = 16s + (lane&15), col(halfs) = dbase + (lane>>4)*8.
    float oacc[4][4];
    #pragma unroll
    for (int d = 0; d < 4; d++)
        #pragma unroll
        for (int r = 0; r < 4; r++) oacc[d][r] = 0.f;

    const uint32_t vBase = smem_u32(&Vs[hh][0]) +
                           (uint32_t)(((lane & 15) * 40 + (lane >> 4) * 8) * 2);

    #pragma unroll
    for (int s = 0; s < 4; s++) {
        const int t0 = 2 * s, t1 = 2 * s + 1;
        const uint32_t pa0 = f2u(sacc[t0][0] * inv0, sacc[t0][1] * inv0);
        const uint32_t pa1 = f2u(sacc[t0][2] * inv1, sacc[t0][3] * inv1);
        const uint32_t pa2 = (t1 < 7) ? f2u(sacc[t1][0] * inv0, sacc[t1][1] * inv0) : 0u;
        const uint32_t pa3 = (t1 < 7) ? f2u(sacc[t1][2] * inv1, sacc[t1][3] * inv1) : 0u;

        uint32_t v0[4], v1[4];
        const uint32_t rowoff = (uint32_t)(16 * s * 40 * 2);
        ldsm_x4_trans(v0, vBase + rowoff);            // d 0-15
        ldsm_x4_trans(v1, vBase + rowoff + 32);       // d 16-31 (16 halfs)

        mma16816(oacc[0], pa0, pa1, pa2, pa3, v0[0], v0[1]);   // d 0-7
        mma16816(oacc[1], pa0, pa1, pa2, pa3, v0[2], v0[3]);   // d 8-15
        mma16816(oacc[2], pa0, pa1, pa2, pa3, v1[0], v1[1]);   // d 16-23
        mma16816(oacc[3], pa0, pa1, pa2, pa3, v1[2], v1[3]);   // d 24-31
    }

    #pragma unroll
    for (int d = 0; d < 4; d++) {
        const int dc = 8 * d + 2 * tg;
        if (i0 < NTOK) {
            __half2 o = __floats2half2_rn(oacc[d][0], oacc[d][1]);
            *(__half2*)(oh + (size_t)(b * NTOK + i0) * DIM + (size_t)h * HDIM + dc) = o;
        }
        if (i1 < NTOK) {
            __half2 o = __floats2half2_rn(oacc[d][2], oacc[d][3]);
            *(__half2*)(oh + (size_t)(b * NTOK + i1) * DIM + (size_t)h * HDIM + dc) = o;
        }
    }
}

// ---------------------------------------------------------------------------
extern "C" void kernel_launch(void* const* d_in, const int* in_sizes, int n_in,
                              void* d_out, int out_size) {
    const float* x          = (const float*)d_in[0];
    const float* mask       = (const float*)d_in[1];
    const float* qkv_w      = (const float*)d_in[2];
    const float* qkv_b      = (const float*)d_in[3];
    const float* proj_w     = (const float*)d_in[4];
    const float* proj_b     = (const float*)d_in[5];
    const float* bias_table = (const float*)d_in[6];
    float* out = (float*)d_out;

    __half *xh, *wq, *wp, *ah, *qkvh;
    cudaGetSymbolAddress((void**)&xh, g_xh);
    cudaGetSymbolAddress((void**)&wq, g_wq);
    cudaGetSymbolAddress((void**)&wp, g_wp);
    cudaGetSymbolAddress((void**)&ah, g_ah);
    cudaGetSymbolAddress((void**)&qkvh, g_qkvh);

    cudaFuncSetAttribute(gemm_mma<true>,
                         cudaFuncAttributeMaxDynamicSharedMemorySize, GEMM_SMEM);
    cudaFuncSetAttribute(gemm_mma<false>,
                         cudaFuncAttributeMaxDynamicSharedMemorySize, GEMM_SMEM);

    {   // x -> fp16
        const size_t n4 = (size_t)MROWS * KD / 4;
        convert_x_kernel<<<(unsigned)((n4 + 255) / 256), 256>>>(x, xh, n4);
    }
    {   // both weights: transpose + fp16, one launch
        const int tot = KD * QKVCOLS + KD * DIM;
        convert_w2_kernel<<<(tot + 255) / 256, 256>>>(qkv_w, wq, proj_w, wp);
    }
    {   // QKV GEMM (tensor cores) -> fp16 intermediate
        dim3 grid(QKVCOLS / 128, MROWS / 128);
        gemm_mma<true><<<grid, 128, GEMM_SMEM>>>(xh, wq, qkv_b, qkvh, QKVCOLS);
    }
    {   // attention (tensor cores): 2 heads per 256-thread block
        dim3 grid(BATCH, NHEAD / 2);
        window_attn_kernel<<<grid, 256>>>(qkvh, mask, bias_table, ah);
    }
    {   // proj GEMM (tensor cores) -> fp32 output
        dim3 grid(DIM / 128, MROWS / 128);
        gemm_mma<false><<<grid, 128, GEMM_SMEM>>>(ah, wp, proj_b, out, DIM);
    }
}